// round 1
// baseline (speedup 1.0000x reference)
#include <cuda_runtime.h>
#include <cstdint>
#include <cstddef>

// Problem constants (shapes fixed by the dataset; runtime sizes still derived
// from in_sizes and guarded).
#define MAXN 50000
#define MAXE 800000
#define NF   128
#define NOUT 64

// Scratch (no allocations allowed -> __device__ globals).
__device__ float g_y1[(size_t)MAXN * NF];   // x @ W1^T
__device__ float g_s1[(size_t)MAXN * NF];   // spmm(y1)
__device__ float g_y2[(size_t)MAXN * NOUT]; // relu(s1) @ W2^T
__device__ float g_s2[(size_t)MAXN * NOUT]; // spmm(y2)

// ---------------------------------------------------------------------------
// Vector reduction to global memory (sm_90+): 4x fewer atomic ops than scalar.
// ---------------------------------------------------------------------------
__device__ __forceinline__ void red_add_v4(float* addr, float4 v) {
    asm volatile("red.global.add.v4.f32 [%0], {%1, %2, %3, %4};"
                 :: "l"(addr), "f"(v.x), "f"(v.y), "f"(v.z), "f"(v.w)
                 : "memory");
}

// ---------------------------------------------------------------------------
// Zero-fill two buffers (s1, s2) with float4 stores.
// ---------------------------------------------------------------------------
__global__ void zero_kernel(float4* a, int n4a, float4* b, int n4b) {
    int i = blockIdx.x * blockDim.x + threadIdx.x;
    int stride = gridDim.x * blockDim.x;
    float4 z = make_float4(0.f, 0.f, 0.f, 0.f);
    for (int k = i; k < n4a; k += stride) a[k] = z;
    for (int k = i; k < n4b; k += stride) b[k] = z;
}

// ---------------------------------------------------------------------------
// C[M, NCOLS] = act(A)[M, 128] @ W[NCOLS, 128]^T
// Register-tiled fp32 GEMM: BM=128, BN=NCOLS, BK=8, 256 threads, 8xTN per thread.
// RELU_IN applies relu to A on load (fuses layer-1 activation into layer-2 GEMM).
// ---------------------------------------------------------------------------
template <int NCOLS, bool RELU_IN>
__global__ __launch_bounds__(256) void gemm_nt_kernel(
    const float* __restrict__ A, const float* __restrict__ W,
    float* __restrict__ C, int M)
{
    constexpr int BK   = 8;
    constexpr int TN   = NCOLS / 16;                 // 8 (NCOLS=128) or 4 (NCOLS=64)
    constexpr int APAD = 132;                        // pad to kill STS bank conflicts
    constexpr int BPAD = (NCOLS == 128) ? 132 : 68;
    __shared__ float As[BK * APAD];
    __shared__ float Bs[BK * BPAD];

    const int tid = threadIdx.x;
    const int tx  = tid & 15;
    const int ty  = tid >> 4;
    const int blockRow = blockIdx.x * 128;

    float acc[8][TN];
#pragma unroll
    for (int i = 0; i < 8; ++i)
#pragma unroll
        for (int j = 0; j < TN; ++j) acc[i][j] = 0.f;

    const int  arow  = tid >> 1;          // 0..127
    const int  akoff = (tid & 1) * 4;     // 0 or 4
    const int  gArow = blockRow + arow;
    const bool aok   = (gArow < M);

    for (int k0 = 0; k0 < 128; k0 += BK) {
        // Stage A tile (128 rows x 8 k), transposed into As[k][m].
        float4 av = make_float4(0.f, 0.f, 0.f, 0.f);
        if (aok)
            av = *reinterpret_cast<const float4*>(A + (size_t)gArow * 128 + k0 + akoff);
        if (RELU_IN) {
            av.x = fmaxf(av.x, 0.f); av.y = fmaxf(av.y, 0.f);
            av.z = fmaxf(av.z, 0.f); av.w = fmaxf(av.w, 0.f);
        }
        As[(akoff + 0) * APAD + arow] = av.x;
        As[(akoff + 1) * APAD + arow] = av.y;
        As[(akoff + 2) * APAD + arow] = av.z;
        As[(akoff + 3) * APAD + arow] = av.w;

        // Stage W tile (NCOLS rows x 8 k), transposed into Bs[k][j].
        if (NCOLS == 128 || tid < 128) {
            int j    = tid >> 1;
            int koff = (tid & 1) * 4;
            float4 bv = *reinterpret_cast<const float4*>(W + (size_t)j * 128 + k0 + koff);
            Bs[(koff + 0) * BPAD + j] = bv.x;
            Bs[(koff + 1) * BPAD + j] = bv.y;
            Bs[(koff + 2) * BPAD + j] = bv.z;
            Bs[(koff + 3) * BPAD + j] = bv.w;
        }
        __syncthreads();

#pragma unroll
        for (int k = 0; k < BK; ++k) {
            float a[8];
            float4 a0 = *reinterpret_cast<const float4*>(&As[k * APAD + ty * 8]);
            float4 a1 = *reinterpret_cast<const float4*>(&As[k * APAD + ty * 8 + 4]);
            a[0] = a0.x; a[1] = a0.y; a[2] = a0.z; a[3] = a0.w;
            a[4] = a1.x; a[5] = a1.y; a[6] = a1.z; a[7] = a1.w;
            float b[TN];
            float4 b0 = *reinterpret_cast<const float4*>(&Bs[k * BPAD + tx * TN]);
            b[0] = b0.x; b[1] = b0.y; b[2] = b0.z; b[3] = b0.w;
            if constexpr (TN == 8) {
                float4 b1 = *reinterpret_cast<const float4*>(&Bs[k * BPAD + tx * TN + 4]);
                b[4] = b1.x; b[5] = b1.y; b[6] = b1.z; b[7] = b1.w;
            }
#pragma unroll
            for (int i = 0; i < 8; ++i)
#pragma unroll
                for (int j = 0; j < TN; ++j)
                    acc[i][j] = fmaf(a[i], b[j], acc[i][j]);
        }
        __syncthreads();
    }

#pragma unroll
    for (int i = 0; i < 8; ++i) {
        int row = blockRow + ty * 8 + i;
        if (row < M) {
#pragma unroll
            for (int c = 0; c < TN; c += 4) {
                float4 o = make_float4(acc[i][c], acc[i][c + 1], acc[i][c + 2], acc[i][c + 3]);
                *reinterpret_cast<float4*>(C + (size_t)row * NCOLS + tx * TN + c) = o;
            }
        }
    }
}

// ---------------------------------------------------------------------------
// Scatter SPMM, 128 floats/row: one warp per edge, red.v4 per lane.
// S[dst[e]] += vals[e] * Y[src[e]]
// ---------------------------------------------------------------------------
__global__ void spmm128_kernel(const float* __restrict__ Y, const float* __restrict__ vals,
                               const int* __restrict__ src, const int* __restrict__ dst,
                               float* __restrict__ S, int E)
{
    int gid  = blockIdx.x * blockDim.x + threadIdx.x;
    int e    = gid >> 5;
    int lane = threadIdx.x & 31;
    if (e >= E) return;
    int   s = __ldg(src + e);
    int   d = __ldg(dst + e);
    float v = __ldg(vals + e);
    float4 f = *reinterpret_cast<const float4*>(Y + (size_t)s * 128 + lane * 4);
    f.x *= v; f.y *= v; f.z *= v; f.w *= v;
    red_add_v4(S + (size_t)d * 128 + lane * 4, f);
}

// Scatter SPMM, 64 floats/row: 16 lanes per edge (2 edges per warp).
__global__ void spmm64_kernel(const float* __restrict__ Y, const float* __restrict__ vals,
                              const int* __restrict__ src, const int* __restrict__ dst,
                              float* __restrict__ S, int E)
{
    int gid = blockIdx.x * blockDim.x + threadIdx.x;
    int e   = gid >> 4;
    int sub = gid & 15;
    if (e >= E) return;
    int   s = __ldg(src + e);
    int   d = __ldg(dst + e);
    float v = __ldg(vals + e);
    float4 f = *reinterpret_cast<const float4*>(Y + (size_t)s * 64 + sub * 4);
    f.x *= v; f.y *= v; f.z *= v; f.w *= v;
    red_add_v4(S + (size_t)d * 64 + sub * 4, f);
}

// ---------------------------------------------------------------------------
// Row softmax over [M, 64]: one warp per row, 2 floats/lane.
// ---------------------------------------------------------------------------
__global__ void softmax_kernel(const float* __restrict__ S, float* __restrict__ out, int M)
{
    int gid  = blockIdx.x * blockDim.x + threadIdx.x;
    int row  = gid >> 5;
    int lane = threadIdx.x & 31;
    if (row >= M) return;
    float2 v = *reinterpret_cast<const float2*>(S + (size_t)row * 64 + lane * 2);
    float m = fmaxf(v.x, v.y);
#pragma unroll
    for (int o = 16; o; o >>= 1) m = fmaxf(m, __shfl_xor_sync(0xffffffffu, m, o));
    float e0 = __expf(v.x - m);
    float e1 = __expf(v.y - m);
    float ssum = e0 + e1;
#pragma unroll
    for (int o = 16; o; o >>= 1) ssum += __shfl_xor_sync(0xffffffffu, ssum, o);
    float inv = 1.f / ssum;
    *reinterpret_cast<float2*>(out + (size_t)row * 64 + lane * 2) = make_float2(e0 * inv, e1 * inv);
}

// ---------------------------------------------------------------------------
// Launch. Inputs (metadata order): x, vals, W1, W2, src, dst. Output fp32 [N,64].
// ---------------------------------------------------------------------------
extern "C" void kernel_launch(void* const* d_in, const int* in_sizes, int n_in,
                              void* d_out, int out_size)
{
    const float* x    = (const float*)d_in[0];
    const float* vals = (const float*)d_in[1];
    const float* W1   = (const float*)d_in[2];
    const float* W2   = (const float*)d_in[3];
    const int*   src  = (const int*)d_in[4];
    const int*   dst  = (const int*)d_in[5];
    float*       out  = (float*)d_out;

    const int M = in_sizes[0] / NF;   // 50000
    const int E = in_sizes[1];        // 800000

    float *y1, *s1, *y2, *s2;
    cudaGetSymbolAddress((void**)&y1, g_y1);
    cudaGetSymbolAddress((void**)&s1, g_s1);
    cudaGetSymbolAddress((void**)&y2, g_y2);
    cudaGetSymbolAddress((void**)&s2, g_s2);

    // 1. zero the accumulation buffers
    zero_kernel<<<1184, 256>>>((float4*)s1, M * (NF / 4), (float4*)s2, M * (NOUT / 4));

    // 2. y1 = x @ W1^T
    int gemmBlocks = (M + 127) / 128;
    gemm_nt_kernel<128, false><<<gemmBlocks, 256>>>(x, W1, y1, M);

    // 3. s1 = spmm(y1)   (warp per edge)
    spmm128_kernel<<<(E * 32 + 255) / 256, 256>>>(y1, vals, src, dst, s1, E);

    // 4. y2 = relu(s1) @ W2^T
    gemm_nt_kernel<64, true><<<gemmBlocks, 256>>>(s1, W2, y2, M);

    // 5. s2 = spmm(y2)   (16 lanes per edge)
    spmm64_kernel<<<(E * 16 + 255) / 256, 256>>>(y2, vals, src, dst, s2, E);

    // 6. out = softmax(s2, dim=1)
    softmax_kernel<<<(M * 32 + 255) / 256, 256>>>(s2, out, M);
}

// round 3
// speedup vs baseline: 1.4399x; 1.4399x over previous
#include <cuda_runtime.h>
#include <cstdint>
#include <cstddef>

#define MAXN 50000
#define MAXE 800000
#define NF   128
#define NOUT 64
#define SCAN_B 512

// Scratch (no allocations allowed -> __device__ globals).
__device__ float g_y1[(size_t)MAXN * NF];     // x @ W1^T
__device__ float g_s1[(size_t)MAXN * NF];     // gather-spmm(y1)
__device__ float g_y2[(size_t)MAXN * NOUT];   // relu(s1) @ W2^T
__device__ int   g_deg[MAXN];                 // degree counts, then write-cursor
__device__ int   g_off[MAXN + 1];             // CSR row offsets (by dst)
__device__ int   g_bsum[SCAN_B];              // scan block sums
__device__ int2  g_edges[MAXE];               // packed {src, __float_as_int(val)} sorted by dst

// ---------------------------------------------------------------------------
// CSR build: histogram -> exclusive scan (3 kernels) -> permute
// ---------------------------------------------------------------------------
__global__ void hist_kernel(const int* __restrict__ dst, int E) {
    int i = blockIdx.x * blockDim.x + threadIdx.x;
    if (i < E) atomicAdd(&g_deg[__ldg(dst + i)], 1);
}

__global__ __launch_bounds__(SCAN_B) void scan1_kernel(int n) {
    __shared__ int sh[SCAN_B];
    int t = threadIdx.x;
    int i = blockIdx.x * SCAN_B + t;
    int v = (i < n) ? g_deg[i] : 0;
    sh[t] = v;
    __syncthreads();
#pragma unroll
    for (int o = 1; o < SCAN_B; o <<= 1) {
        int u = (t >= o) ? sh[t - o] : 0;
        __syncthreads();
        sh[t] += u;
        __syncthreads();
    }
    if (i <= n && i < MAXN + 1) g_off[i] = sh[t] - v;   // block-local exclusive
    if (t == SCAN_B - 1) g_bsum[blockIdx.x] = sh[t];
}

__global__ __launch_bounds__(SCAN_B) void scan2_kernel(int nb) {
    __shared__ int sh[SCAN_B];
    int t = threadIdx.x;
    int v = (t < nb) ? g_bsum[t] : 0;
    sh[t] = v;
    __syncthreads();
#pragma unroll
    for (int o = 1; o < SCAN_B; o <<= 1) {
        int u = (t >= o) ? sh[t - o] : 0;
        __syncthreads();
        sh[t] += u;
        __syncthreads();
    }
    if (t < nb) g_bsum[t] = sh[t] - v;                  // exclusive block prefix
}

__global__ void scan3_kernel(int n, int E) {
    int i = blockIdx.x * blockDim.x + threadIdx.x;
    if (i < n) {
        int o = g_off[i] + g_bsum[i >> 9];
        g_off[i] = o;
        g_deg[i] = o;                                   // reuse deg[] as write cursor
    }
    if (i == 0) g_off[n] = E;
}

__global__ void permute_kernel(const int* __restrict__ src, const int* __restrict__ dst,
                               const float* __restrict__ vals, int E) {
    int e = blockIdx.x * blockDim.x + threadIdx.x;
    if (e >= E) return;
    int pos = atomicAdd(&g_deg[__ldg(dst + e)], 1);
    g_edges[pos] = make_int2(__ldg(src + e), __float_as_int(__ldg(vals + e)));
}

// ---------------------------------------------------------------------------
// C[M, NCOLS] = act(A)[M, 128] @ W[NCOLS, 128]^T
// Register-tiled fp32 GEMM: BM=128, BN=NCOLS, BK=8, 256 threads.
// ---------------------------------------------------------------------------
template <int NCOLS, bool RELU_IN>
__global__ __launch_bounds__(256) void gemm_nt_kernel(
    const float* __restrict__ A, const float* __restrict__ W,
    float* __restrict__ C, int M)
{
    constexpr int BK   = 8;
    constexpr int TN   = NCOLS / 16;
    constexpr int APAD = 132;
    constexpr int BPAD = (NCOLS == 128) ? 132 : 68;
    __shared__ float As[BK * APAD];
    __shared__ float Bs[BK * BPAD];

    const int tid = threadIdx.x;
    const int tx  = tid & 15;
    const int ty  = tid >> 4;
    const int blockRow = blockIdx.x * 128;

    float acc[8][TN];
#pragma unroll
    for (int i = 0; i < 8; ++i)
#pragma unroll
        for (int j = 0; j < TN; ++j) acc[i][j] = 0.f;

    const int  arow  = tid >> 1;
    const int  akoff = (tid & 1) * 4;
    const int  gArow = blockRow + arow;
    const bool aok   = (gArow < M);

    for (int k0 = 0; k0 < 128; k0 += BK) {
        float4 av = make_float4(0.f, 0.f, 0.f, 0.f);
        if (aok)
            av = *reinterpret_cast<const float4*>(A + (size_t)gArow * 128 + k0 + akoff);
        if (RELU_IN) {
            av.x = fmaxf(av.x, 0.f); av.y = fmaxf(av.y, 0.f);
            av.z = fmaxf(av.z, 0.f); av.w = fmaxf(av.w, 0.f);
        }
        As[(akoff + 0) * APAD + arow] = av.x;
        As[(akoff + 1) * APAD + arow] = av.y;
        As[(akoff + 2) * APAD + arow] = av.z;
        As[(akoff + 3) * APAD + arow] = av.w;

        if (NCOLS == 128 || tid < 128) {
            int j    = tid >> 1;
            int koff = (tid & 1) * 4;
            float4 bv = *reinterpret_cast<const float4*>(W + (size_t)j * 128 + k0 + koff);
            Bs[(koff + 0) * BPAD + j] = bv.x;
            Bs[(koff + 1) * BPAD + j] = bv.y;
            Bs[(koff + 2) * BPAD + j] = bv.z;
            Bs[(koff + 3) * BPAD + j] = bv.w;
        }
        __syncthreads();

#pragma unroll
        for (int k = 0; k < BK; ++k) {
            float a[8];
            float4 a0 = *reinterpret_cast<const float4*>(&As[k * APAD + ty * 8]);
            float4 a1 = *reinterpret_cast<const float4*>(&As[k * APAD + ty * 8 + 4]);
            a[0] = a0.x; a[1] = a0.y; a[2] = a0.z; a[3] = a0.w;
            a[4] = a1.x; a[5] = a1.y; a[6] = a1.z; a[7] = a1.w;
            float b[TN];
            float4 b0 = *reinterpret_cast<const float4*>(&Bs[k * BPAD + tx * TN]);
            b[0] = b0.x; b[1] = b0.y; b[2] = b0.z; b[3] = b0.w;
            if constexpr (TN == 8) {
                float4 b1 = *reinterpret_cast<const float4*>(&Bs[k * BPAD + tx * TN + 4]);
                b[4] = b1.x; b[5] = b1.y; b[6] = b1.z; b[7] = b1.w;
            }
#pragma unroll
            for (int i = 0; i < 8; ++i)
#pragma unroll
                for (int j = 0; j < TN; ++j)
                    acc[i][j] = fmaf(a[i], b[j], acc[i][j]);
        }
        __syncthreads();
    }

#pragma unroll
    for (int i = 0; i < 8; ++i) {
        int row = blockRow + ty * 8 + i;
        if (row < M) {
#pragma unroll
            for (int c = 0; c < TN; c += 4) {
                float4 o = make_float4(acc[i][c], acc[i][c + 1], acc[i][c + 2], acc[i][c + 3]);
                *reinterpret_cast<float4*>(C + (size_t)row * NCOLS + tx * TN + c) = o;
            }
        }
    }
}

// ---------------------------------------------------------------------------
// Gather SPMM, 128-wide: one warp per dst node. acc in registers, single store.
// ---------------------------------------------------------------------------
__global__ __launch_bounds__(256) void gather128_kernel(
    const float* __restrict__ Y, float* __restrict__ S, int n)
{
    int gid  = blockIdx.x * blockDim.x + threadIdx.x;
    int d    = gid >> 5;
    int lane = threadIdx.x & 31;
    if (d >= n) return;
    int beg = g_off[d], end = g_off[d + 1];

    float4 acc = make_float4(0.f, 0.f, 0.f, 0.f);
    int e = beg;
    for (; e + 1 < end; e += 2) {            // 2-way unroll for MLP
        int2 p0 = __ldg(&g_edges[e]);
        int2 p1 = __ldg(&g_edges[e + 1]);
        float v0 = __int_as_float(p0.y);
        float v1 = __int_as_float(p1.y);
        float4 f0 = *reinterpret_cast<const float4*>(Y + (size_t)p0.x * 128 + lane * 4);
        float4 f1 = *reinterpret_cast<const float4*>(Y + (size_t)p1.x * 128 + lane * 4);
        acc.x = fmaf(v0, f0.x, acc.x); acc.y = fmaf(v0, f0.y, acc.y);
        acc.z = fmaf(v0, f0.z, acc.z); acc.w = fmaf(v0, f0.w, acc.w);
        acc.x = fmaf(v1, f1.x, acc.x); acc.y = fmaf(v1, f1.y, acc.y);
        acc.z = fmaf(v1, f1.z, acc.z); acc.w = fmaf(v1, f1.w, acc.w);
    }
    if (e < end) {
        int2 p = __ldg(&g_edges[e]);
        float v = __int_as_float(p.y);
        float4 f = *reinterpret_cast<const float4*>(Y + (size_t)p.x * 128 + lane * 4);
        acc.x = fmaf(v, f.x, acc.x); acc.y = fmaf(v, f.y, acc.y);
        acc.z = fmaf(v, f.z, acc.z); acc.w = fmaf(v, f.w, acc.w);
    }
    *reinterpret_cast<float4*>(S + (size_t)d * 128 + lane * 4) = acc;
}

// ---------------------------------------------------------------------------
// Gather SPMM, 64-wide, fused with row softmax: warp per node, 2 floats/lane.
// ---------------------------------------------------------------------------
__global__ __launch_bounds__(256) void gather64_softmax_kernel(
    const float* __restrict__ Y, float* __restrict__ out, int n)
{
    int gid  = blockIdx.x * blockDim.x + threadIdx.x;
    int d    = gid >> 5;
    int lane = threadIdx.x & 31;
    if (d >= n) return;
    int beg = g_off[d], end = g_off[d + 1];

    float2 acc = make_float2(0.f, 0.f);
    int e = beg;
    for (; e + 1 < end; e += 2) {
        int2 p0 = __ldg(&g_edges[e]);
        int2 p1 = __ldg(&g_edges[e + 1]);
        float v0 = __int_as_float(p0.y);
        float v1 = __int_as_float(p1.y);
        float2 f0 = *reinterpret_cast<const float2*>(Y + (size_t)p0.x * 64 + lane * 2);
        float2 f1 = *reinterpret_cast<const float2*>(Y + (size_t)p1.x * 64 + lane * 2);
        acc.x = fmaf(v0, f0.x, acc.x); acc.y = fmaf(v0, f0.y, acc.y);
        acc.x = fmaf(v1, f1.x, acc.x); acc.y = fmaf(v1, f1.y, acc.y);
    }
    if (e < end) {
        int2 p = __ldg(&g_edges[e]);
        float v = __int_as_float(p.y);
        float2 f = *reinterpret_cast<const float2*>(Y + (size_t)p.x * 64 + lane * 2);
        acc.x = fmaf(v, f.x, acc.x); acc.y = fmaf(v, f.y, acc.y);
    }

    // warp softmax over the 64-value row (2 per lane)
    float m = fmaxf(acc.x, acc.y);
#pragma unroll
    for (int o = 16; o; o >>= 1) m = fmaxf(m, __shfl_xor_sync(0xffffffffu, m, o));
    float e0 = __expf(acc.x - m);
    float e1 = __expf(acc.y - m);
    float ssum = e0 + e1;
#pragma unroll
    for (int o = 16; o; o >>= 1) ssum += __shfl_xor_sync(0xffffffffu, ssum, o);
    float inv = 1.f / ssum;
    *reinterpret_cast<float2*>(out + (size_t)d * 64 + lane * 2) =
        make_float2(e0 * inv, e1 * inv);
}

// ---------------------------------------------------------------------------
// Launch. Inputs: x, vals, W1, W2, src, dst. Output fp32 [N, 64].
// ---------------------------------------------------------------------------
extern "C" void kernel_launch(void* const* d_in, const int* in_sizes, int n_in,
                              void* d_out, int out_size)
{
    const float* x    = (const float*)d_in[0];
    const float* vals = (const float*)d_in[1];
    const float* W1   = (const float*)d_in[2];
    const float* W2   = (const float*)d_in[3];
    const int*   src  = (const int*)d_in[4];
    const int*   dst  = (const int*)d_in[5];
    float*       out  = (float*)d_out;

    const int M = in_sizes[0] / NF;   // 50000
    const int E = in_sizes[1];        // 800000

    float *y1, *s1, *y2;
    int* degp;
    cudaGetSymbolAddress((void**)&y1, g_y1);
    cudaGetSymbolAddress((void**)&s1, g_s1);
    cudaGetSymbolAddress((void**)&y2, g_y2);
    cudaGetSymbolAddress((void**)&degp, g_deg);

    // --- CSR build (by dst) ---
    cudaMemsetAsync(degp, 0, M * sizeof(int));
    hist_kernel<<<(E + 255) / 256, 256>>>(dst, E);
    int nb = (M + SCAN_B - 1) / SCAN_B;                 // 98
    scan1_kernel<<<nb, SCAN_B>>>(M);
    scan2_kernel<<<1, SCAN_B>>>(nb);
    scan3_kernel<<<(M + 255) / 256, 256>>>(M, E);
    permute_kernel<<<(E + 255) / 256, 256>>>(src, dst, vals, E);

    // --- pipeline ---
    int gemmBlocks = (M + 127) / 128;
    gemm_nt_kernel<128, false><<<gemmBlocks, 256>>>(x, W1, y1, M);          // y1 = x @ W1^T
    gather128_kernel<<<(M * 32 + 255) / 256, 256>>>(y1, s1, M);             // s1 = A @ y1
    gemm_nt_kernel<64, true><<<gemmBlocks, 256>>>(s1, W2, y2, M);           // y2 = relu(s1) @ W2^T
    gather64_softmax_kernel<<<(M * 32 + 255) / 256, 256>>>(y2, out, M);     // out = softmax(A @ y2)
}

// round 4
// speedup vs baseline: 1.4578x; 1.0124x over previous
#include <cuda_runtime.h>
#include <cstdint>
#include <cstddef>

#define MAXN 50000
#define MAXE 800000
#define NF   128
#define NOUT 64
#define SCAN_B 512

// Scratch (no allocations allowed -> __device__ globals).
__device__ float g_y1[(size_t)MAXN * NF];     // x @ W1^T
__device__ float g_s1[(size_t)MAXN * NF];     // gather-spmm(y1)
__device__ float g_y2[(size_t)MAXN * NOUT];   // relu(s1) @ W2^T
__device__ int   g_deg[MAXN];                 // degree counts, then write-cursor
__device__ int   g_off[MAXN + 1];             // CSR row offsets (by dst)
__device__ int   g_bsum[SCAN_B];              // scan block sums
__device__ int2  g_edges[MAXE];               // packed {src, __float_as_int(val)} by dst

// ---------------------------------------------------------------------------
// CSR build: histogram -> exclusive scan (3 kernels) -> permute
// ---------------------------------------------------------------------------
__global__ void hist_kernel(const int* __restrict__ dst, int E) {
    int i = blockIdx.x * blockDim.x + threadIdx.x;
    if (i < E) atomicAdd(&g_deg[__ldg(dst + i)], 1);
}

__global__ __launch_bounds__(SCAN_B) void scan1_kernel(int n) {
    __shared__ int sh[SCAN_B];
    int t = threadIdx.x;
    int i = blockIdx.x * SCAN_B + t;
    int v = (i < n) ? g_deg[i] : 0;
    sh[t] = v;
    __syncthreads();
#pragma unroll
    for (int o = 1; o < SCAN_B; o <<= 1) {
        int u = (t >= o) ? sh[t - o] : 0;
        __syncthreads();
        sh[t] += u;
        __syncthreads();
    }
    if (i <= n && i < MAXN + 1) g_off[i] = sh[t] - v;   // block-local exclusive
    if (t == SCAN_B - 1) g_bsum[blockIdx.x] = sh[t];
}

__global__ __launch_bounds__(SCAN_B) void scan2_kernel(int nb) {
    __shared__ int sh[SCAN_B];
    int t = threadIdx.x;
    int v = (t < nb) ? g_bsum[t] : 0;
    sh[t] = v;
    __syncthreads();
#pragma unroll
    for (int o = 1; o < SCAN_B; o <<= 1) {
        int u = (t >= o) ? sh[t - o] : 0;
        __syncthreads();
        sh[t] += u;
        __syncthreads();
    }
    if (t < nb) g_bsum[t] = sh[t] - v;                  // exclusive block prefix
}

__global__ void scan3_kernel(int n, int E) {
    int i = blockIdx.x * blockDim.x + threadIdx.x;
    if (i < n) {
        int o = g_off[i] + g_bsum[i >> 9];
        g_off[i] = o;
        g_deg[i] = o;                                   // reuse deg[] as write cursor
    }
    if (i == 0) g_off[n] = E;
}

__global__ void permute_kernel(const int* __restrict__ src, const int* __restrict__ dst,
                               const float* __restrict__ vals, int E) {
    int e = blockIdx.x * blockDim.x + threadIdx.x;
    if (e >= E) return;
    int pos = atomicAdd(&g_deg[__ldg(dst + e)], 1);
    g_edges[pos] = make_int2(__ldg(src + e), __float_as_int(__ldg(vals + e)));
}

// ---------------------------------------------------------------------------
// C[M, NCOLS] = act(A)[M, 128] @ W[NCOLS, 128]^T
// Double-buffered register-staged SGEMM: BM=128, BN=NCOLS, BK=8, 256 threads.
// One __syncthreads per k-tile; GMEM prefetch overlapped with compute.
// ---------------------------------------------------------------------------
template <int NCOLS, bool RELU_IN>
__global__ __launch_bounds__(256) void gemm_nt_kernel(
    const float* __restrict__ A, const float* __restrict__ W,
    float* __restrict__ C, int M)
{
    constexpr int BK    = 8;
    constexpr int NTILE = 128 / BK;                  // 16
    constexpr int TN    = NCOLS / 16;                // 8 or 4
    constexpr int APAD  = 132;
    constexpr int BPAD  = (NCOLS == 128) ? 132 : 68;
    __shared__ float As[2][BK * APAD];
    __shared__ float Bs[2][BK * BPAD];

    const int tid = threadIdx.x;
    const int tx  = tid & 15;
    const int ty  = tid >> 4;
    const int blockRow = blockIdx.x * 128;

    float acc[8][TN];
#pragma unroll
    for (int i = 0; i < 8; ++i)
#pragma unroll
        for (int j = 0; j < TN; ++j) acc[i][j] = 0.f;

    const int  arow  = tid >> 1;          // 0..127
    const int  akoff = (tid & 1) * 4;     // 0 or 4
    const int  gArow = blockRow + arow;
    const bool aok   = (gArow < M);
    const bool bok   = (NCOLS == 128) || (tid < 128);
    const int  brow  = tid >> 1;
    const int  bkoff = (tid & 1) * 4;

    auto loadA = [&](int k0) -> float4 {
        float4 av = make_float4(0.f, 0.f, 0.f, 0.f);
        if (aok)
            av = *reinterpret_cast<const float4*>(A + (size_t)gArow * 128 + k0 + akoff);
        if (RELU_IN) {
            av.x = fmaxf(av.x, 0.f); av.y = fmaxf(av.y, 0.f);
            av.z = fmaxf(av.z, 0.f); av.w = fmaxf(av.w, 0.f);
        }
        return av;
    };
    auto loadB = [&](int k0) -> float4 {
        if (bok)
            return *reinterpret_cast<const float4*>(W + (size_t)brow * 128 + k0 + bkoff);
        return make_float4(0.f, 0.f, 0.f, 0.f);
    };
    auto storeA = [&](int buf, float4 av) {
        As[buf][(akoff + 0) * APAD + arow] = av.x;
        As[buf][(akoff + 1) * APAD + arow] = av.y;
        As[buf][(akoff + 2) * APAD + arow] = av.z;
        As[buf][(akoff + 3) * APAD + arow] = av.w;
    };
    auto storeB = [&](int buf, float4 bv) {
        if (bok) {
            Bs[buf][(bkoff + 0) * BPAD + brow] = bv.x;
            Bs[buf][(bkoff + 1) * BPAD + brow] = bv.y;
            Bs[buf][(bkoff + 2) * BPAD + brow] = bv.z;
            Bs[buf][(bkoff + 3) * BPAD + brow] = bv.w;
        }
    };

    // prologue: stage tile 0
    {
        float4 av = loadA(0);
        float4 bv = loadB(0);
        storeA(0, av);
        storeB(0, bv);
    }
    __syncthreads();

    for (int t = 0; t < NTILE; ++t) {
        const int cur = t & 1;
        float4 av, bv;
        if (t + 1 < NTILE) {                 // issue prefetch early (hidden by compute)
            av = loadA((t + 1) * BK);
            bv = loadB((t + 1) * BK);
        }
#pragma unroll
        for (int k = 0; k < BK; ++k) {
            float a[8];
            float4 a0 = *reinterpret_cast<const float4*>(&As[cur][k * APAD + ty * 8]);
            float4 a1 = *reinterpret_cast<const float4*>(&As[cur][k * APAD + ty * 8 + 4]);
            a[0] = a0.x; a[1] = a0.y; a[2] = a0.z; a[3] = a0.w;
            a[4] = a1.x; a[5] = a1.y; a[6] = a1.z; a[7] = a1.w;
            float b[TN];
            float4 b0 = *reinterpret_cast<const float4*>(&Bs[cur][k * BPAD + tx * TN]);
            b[0] = b0.x; b[1] = b0.y; b[2] = b0.z; b[3] = b0.w;
            if constexpr (TN == 8) {
                float4 b1 = *reinterpret_cast<const float4*>(&Bs[cur][k * BPAD + tx * TN + 4]);
                b[4] = b1.x; b[5] = b1.y; b[6] = b1.z; b[7] = b1.w;
            }
#pragma unroll
            for (int i = 0; i < 8; ++i)
#pragma unroll
                for (int j = 0; j < TN; ++j)
                    acc[i][j] = fmaf(a[i], b[j], acc[i][j]);
        }
        if (t + 1 < NTILE) {
            storeA(cur ^ 1, av);
            storeB(cur ^ 1, bv);
        }
        __syncthreads();
    }

#pragma unroll
    for (int i = 0; i < 8; ++i) {
        int row = blockRow + ty * 8 + i;
        if (row < M) {
#pragma unroll
            for (int c = 0; c < TN; c += 4) {
                float4 o = make_float4(acc[i][c], acc[i][c + 1], acc[i][c + 2], acc[i][c + 3]);
                *reinterpret_cast<float4*>(C + (size_t)row * NCOLS + tx * TN + c) = o;
            }
        }
    }
}

// ---------------------------------------------------------------------------
// Gather SPMM, 128-wide: one warp per dst node, 4-edge unroll for MLP.
// ---------------------------------------------------------------------------
__global__ __launch_bounds__(256) void gather128_kernel(
    const float* __restrict__ Y, float* __restrict__ S, int n)
{
    int gid  = blockIdx.x * blockDim.x + threadIdx.x;
    int d    = gid >> 5;
    int lane = threadIdx.x & 31;
    if (d >= n) return;
    int beg = g_off[d], end = g_off[d + 1];

    float4 acc = make_float4(0.f, 0.f, 0.f, 0.f);
    int e = beg;
    for (; e + 3 < end; e += 4) {
        int2 p0 = __ldg(&g_edges[e]);
        int2 p1 = __ldg(&g_edges[e + 1]);
        int2 p2 = __ldg(&g_edges[e + 2]);
        int2 p3 = __ldg(&g_edges[e + 3]);
        float4 f0 = *reinterpret_cast<const float4*>(Y + (size_t)p0.x * 128 + lane * 4);
        float4 f1 = *reinterpret_cast<const float4*>(Y + (size_t)p1.x * 128 + lane * 4);
        float4 f2 = *reinterpret_cast<const float4*>(Y + (size_t)p2.x * 128 + lane * 4);
        float4 f3 = *reinterpret_cast<const float4*>(Y + (size_t)p3.x * 128 + lane * 4);
        float v0 = __int_as_float(p0.y), v1 = __int_as_float(p1.y);
        float v2 = __int_as_float(p2.y), v3 = __int_as_float(p3.y);
        acc.x = fmaf(v0, f0.x, acc.x); acc.y = fmaf(v0, f0.y, acc.y);
        acc.z = fmaf(v0, f0.z, acc.z); acc.w = fmaf(v0, f0.w, acc.w);
        acc.x = fmaf(v1, f1.x, acc.x); acc.y = fmaf(v1, f1.y, acc.y);
        acc.z = fmaf(v1, f1.z, acc.z); acc.w = fmaf(v1, f1.w, acc.w);
        acc.x = fmaf(v2, f2.x, acc.x); acc.y = fmaf(v2, f2.y, acc.y);
        acc.z = fmaf(v2, f2.z, acc.z); acc.w = fmaf(v2, f2.w, acc.w);
        acc.x = fmaf(v3, f3.x, acc.x); acc.y = fmaf(v3, f3.y, acc.y);
        acc.z = fmaf(v3, f3.z, acc.z); acc.w = fmaf(v3, f3.w, acc.w);
    }
    for (; e < end; ++e) {
        int2 p = __ldg(&g_edges[e]);
        float v = __int_as_float(p.y);
        float4 f = *reinterpret_cast<const float4*>(Y + (size_t)p.x * 128 + lane * 4);
        acc.x = fmaf(v, f.x, acc.x); acc.y = fmaf(v, f.y, acc.y);
        acc.z = fmaf(v, f.z, acc.z); acc.w = fmaf(v, f.w, acc.w);
    }
    *reinterpret_cast<float4*>(S + (size_t)d * 128 + lane * 4) = acc;
}

// ---------------------------------------------------------------------------
// Gather SPMM, 64-wide, fused with row softmax: warp per node, 2 floats/lane.
// ---------------------------------------------------------------------------
__global__ __launch_bounds__(256) void gather64_softmax_kernel(
    const float* __restrict__ Y, float* __restrict__ out, int n)
{
    int gid  = blockIdx.x * blockDim.x + threadIdx.x;
    int d    = gid >> 5;
    int lane = threadIdx.x & 31;
    if (d >= n) return;
    int beg = g_off[d], end = g_off[d + 1];

    float2 acc = make_float2(0.f, 0.f);
    int e = beg;
    for (; e + 3 < end; e += 4) {
        int2 p0 = __ldg(&g_edges[e]);
        int2 p1 = __ldg(&g_edges[e + 1]);
        int2 p2 = __ldg(&g_edges[e + 2]);
        int2 p3 = __ldg(&g_edges[e + 3]);
        float2 f0 = *reinterpret_cast<const float2*>(Y + (size_t)p0.x * 64 + lane * 2);
        float2 f1 = *reinterpret_cast<const float2*>(Y + (size_t)p1.x * 64 + lane * 2);
        float2 f2 = *reinterpret_cast<const float2*>(Y + (size_t)p2.x * 64 + lane * 2);
        float2 f3 = *reinterpret_cast<const float2*>(Y + (size_t)p3.x * 64 + lane * 2);
        float v0 = __int_as_float(p0.y), v1 = __int_as_float(p1.y);
        float v2 = __int_as_float(p2.y), v3 = __int_as_float(p3.y);
        acc.x = fmaf(v0, f0.x, acc.x); acc.y = fmaf(v0, f0.y, acc.y);
        acc.x = fmaf(v1, f1.x, acc.x); acc.y = fmaf(v1, f1.y, acc.y);
        acc.x = fmaf(v2, f2.x, acc.x); acc.y = fmaf(v2, f2.y, acc.y);
        acc.x = fmaf(v3, f3.x, acc.x); acc.y = fmaf(v3, f3.y, acc.y);
    }
    for (; e < end; ++e) {
        int2 p = __ldg(&g_edges[e]);
        float v = __int_as_float(p.y);
        float2 f = *reinterpret_cast<const float2*>(Y + (size_t)p.x * 64 + lane * 2);
        acc.x = fmaf(v, f.x, acc.x); acc.y = fmaf(v, f.y, acc.y);
    }

    // warp softmax over the 64-value row (2 per lane)
    float m = fmaxf(acc.x, acc.y);
#pragma unroll
    for (int o = 16; o; o >>= 1) m = fmaxf(m, __shfl_xor_sync(0xffffffffu, m, o));
    float e0 = __expf(acc.x - m);
    float e1 = __expf(acc.y - m);
    float ssum = e0 + e1;
#pragma unroll
    for (int o = 16; o; o >>= 1) ssum += __shfl_xor_sync(0xffffffffu, ssum, o);
    float inv = 1.f / ssum;
    *reinterpret_cast<float2*>(out + (size_t)d * 64 + lane * 2) =
        make_float2(e0 * inv, e1 * inv);
}

// ---------------------------------------------------------------------------
// Launch. Inputs: x, vals, W1, W2, src, dst. Output fp32 [N, 64].
// ---------------------------------------------------------------------------
extern "C" void kernel_launch(void* const* d_in, const int* in_sizes, int n_in,
                              void* d_out, int out_size)
{
    const float* x    = (const float*)d_in[0];
    const float* vals = (const float*)d_in[1];
    const float* W1   = (const float*)d_in[2];
    const float* W2   = (const float*)d_in[3];
    const int*   src  = (const int*)d_in[4];
    const int*   dst  = (const int*)d_in[5];
    float*       out  = (float*)d_out;

    const int M = in_sizes[0] / NF;   // 50000
    const int E = in_sizes[1];        // 800000

    float *y1, *s1, *y2;
    int* degp;
    cudaGetSymbolAddress((void**)&y1, g_y1);
    cudaGetSymbolAddress((void**)&s1, g_s1);
    cudaGetSymbolAddress((void**)&y2, g_y2);
    cudaGetSymbolAddress((void**)&degp, g_deg);

    // --- CSR build (by dst) ---
    cudaMemsetAsync(degp, 0, M * sizeof(int));
    hist_kernel<<<(E + 255) / 256, 256>>>(dst, E);
    int nb = (M + SCAN_B - 1) / SCAN_B;                 // 98
    scan1_kernel<<<nb, SCAN_B>>>(M);
    scan2_kernel<<<1, SCAN_B>>>(nb);
    scan3_kernel<<<(M + 255) / 256, 256>>>(M, E);
    permute_kernel<<<(E + 255) / 256, 256>>>(src, dst, vals, E);

    // --- pipeline ---
    int gemmBlocks = (M + 127) / 128;
    gemm_nt_kernel<128, false><<<gemmBlocks, 256>>>(x, W1, y1, M);          // y1 = x @ W1^T
    gather128_kernel<<<(M * 32 + 255) / 256, 256>>>(y1, s1, M);             // s1 = A @ y1
    gemm_nt_kernel<64, true><<<gemmBlocks, 256>>>(s1, W2, y2, M);           // y2 = relu(s1) @ W2^T
    gather64_softmax_kernel<<<(M * 32 + 255) / 256, 256>>>(y2, out, M);     // out = softmax(A @ y2)
}

// round 5
// speedup vs baseline: 1.5329x; 1.0515x over previous
#include <cuda_runtime.h>
#include <cstdint>
#include <cstddef>

#define MAXN 50000
#define MAXE 800000
#define NF   128
#define NOUT 64
#define SCAN_B 512

// Scratch (no allocations allowed -> __device__ globals).
__device__ float g_y1[(size_t)MAXN * NF];     // x @ W1^T
__device__ float g_s1[(size_t)MAXN * NF];     // gather-spmm(y1)
__device__ float g_y2[(size_t)MAXN * NOUT];   // relu(s1) @ W2^T
__device__ int   g_deg[MAXN];                 // degree counts, then write-cursor
__device__ int   g_off[MAXN + 1];             // CSR row offsets (by dst)
__device__ int   g_bsum[SCAN_B];              // scan block sums
__device__ int2  g_edges[MAXE];               // packed {src, __float_as_int(val)} by dst

// ---------------------------------------------------------------------------
// CSR build: histogram -> exclusive scan (3 kernels) -> permute
// ---------------------------------------------------------------------------
__global__ void hist_kernel(const int* __restrict__ dst, int E) {
    int i = blockIdx.x * blockDim.x + threadIdx.x;
    if (i < E) atomicAdd(&g_deg[__ldg(dst + i)], 1);
}

__global__ __launch_bounds__(SCAN_B) void scan1_kernel(int n) {
    __shared__ int sh[SCAN_B];
    int t = threadIdx.x;
    int i = blockIdx.x * SCAN_B + t;
    int v = (i < n) ? g_deg[i] : 0;
    sh[t] = v;
    __syncthreads();
#pragma unroll
    for (int o = 1; o < SCAN_B; o <<= 1) {
        int u = (t >= o) ? sh[t - o] : 0;
        __syncthreads();
        sh[t] += u;
        __syncthreads();
    }
    if (i <= n && i < MAXN + 1) g_off[i] = sh[t] - v;   // block-local exclusive
    if (t == SCAN_B - 1) g_bsum[blockIdx.x] = sh[t];
}

__global__ __launch_bounds__(SCAN_B) void scan2_kernel(int nb) {
    __shared__ int sh[SCAN_B];
    int t = threadIdx.x;
    int v = (t < nb) ? g_bsum[t] : 0;
    sh[t] = v;
    __syncthreads();
#pragma unroll
    for (int o = 1; o < SCAN_B; o <<= 1) {
        int u = (t >= o) ? sh[t - o] : 0;
        __syncthreads();
        sh[t] += u;
        __syncthreads();
    }
    if (t < nb) g_bsum[t] = sh[t] - v;                  // exclusive block prefix
}

__global__ void scan3_kernel(int n, int E) {
    int i = blockIdx.x * blockDim.x + threadIdx.x;
    if (i < n) {
        int o = g_off[i] + g_bsum[i >> 9];
        g_off[i] = o;
        g_deg[i] = o;                                   // reuse deg[] as write cursor
    }
    if (i == 0) g_off[n] = E;
}

__global__ void permute_kernel(const int* __restrict__ src, const int* __restrict__ dst,
                               const float* __restrict__ vals, int E) {
    int e = blockIdx.x * blockDim.x + threadIdx.x;
    if (e >= E) return;
    int pos = atomicAdd(&g_deg[__ldg(dst + e)], 1);
    g_edges[pos] = make_int2(__ldg(src + e), __float_as_int(__ldg(vals + e)));
}

// ---------------------------------------------------------------------------
// tf32 helpers
// ---------------------------------------------------------------------------
__device__ __forceinline__ uint32_t f2tf32(float x) {
    uint32_t r;
    asm("cvt.rna.tf32.f32 %0, %1;" : "=r"(r) : "f"(x));
    return r;
}

__device__ __forceinline__ void mma_tf32(float* d, const uint32_t* a, uint32_t b0, uint32_t b1) {
    asm volatile(
        "mma.sync.aligned.m16n8k8.row.col.f32.tf32.tf32.f32 "
        "{%0,%1,%2,%3}, {%4,%5,%6,%7}, {%8,%9}, {%0,%1,%2,%3};"
        : "+f"(d[0]), "+f"(d[1]), "+f"(d[2]), "+f"(d[3])
        : "r"(a[0]), "r"(a[1]), "r"(a[2]), "r"(a[3]), "r"(b0), "r"(b1));
}

// ---------------------------------------------------------------------------
// C[M, NCOLS] = act(A)[M, 128] @ W[NCOLS, 128]^T via 3xTF32 tensor-core MMA.
// BM=128, BK=16, 256 threads (8 warps, 4x2 warp grid; warp tile m32 x NCOLS/2).
// hi/lo split done once at staging; inner loop is LDS + mma only.
// Error ~2^-22 per product -> fp32-level accuracy.
// ---------------------------------------------------------------------------
template <int NCOLS, bool RELU_IN>
__global__ __launch_bounds__(256) void gemm_tc_kernel(
    const float* __restrict__ A, const float* __restrict__ W,
    float* __restrict__ C, int M)
{
    constexpr int BK   = 16;
    constexpr int APAD = 132;           // row-dim pad: (t*PAD+g)%32 unique banks
    constexpr int BPAD = NCOLS + 4;     // 132 or 68 (both ≡ 4 mod 32)
    constexpr int NT   = NCOLS / 16;    // n-tiles per warp: 8 or 4

    __shared__ uint32_t As_hi[BK * APAD];
    __shared__ uint32_t As_lo[BK * APAD];
    __shared__ uint32_t Bs_hi[BK * BPAD];
    __shared__ uint32_t Bs_lo[BK * BPAD];

    const int tid  = threadIdx.x;
    const int wid  = tid >> 5;
    const int lane = tid & 31;
    const int g    = lane >> 2;         // 0..7
    const int t    = lane & 3;          // 0..3
    const int warp_m = wid >> 1;        // 0..3 -> 32 rows each
    const int warp_n = wid & 1;         // 0..1 -> NCOLS/2 cols each
    const int blockRow = blockIdx.x * 128;

    float acc[2][NT][4];
#pragma unroll
    for (int mt = 0; mt < 2; ++mt)
#pragma unroll
        for (int nt = 0; nt < NT; ++nt)
#pragma unroll
            for (int i = 0; i < 4; ++i) acc[mt][nt][i] = 0.f;

    // A staging indices: 128 rows x 16 k, 2 threads/row, 2 float4 each.
    const int  arow  = tid >> 1;
    const int  akoff = (tid & 1) * 8;
    const int  gArow = blockRow + arow;
    const bool aok   = (gArow < M);

    for (int k0 = 0; k0 < 128; k0 += BK) {
        // ---- stage A (with optional relu), split hi/lo ----
        {
            float4 v0 = make_float4(0.f, 0.f, 0.f, 0.f);
            float4 v1 = make_float4(0.f, 0.f, 0.f, 0.f);
            if (aok) {
                v0 = *reinterpret_cast<const float4*>(A + (size_t)gArow * 128 + k0 + akoff);
                v1 = *reinterpret_cast<const float4*>(A + (size_t)gArow * 128 + k0 + akoff + 4);
            }
            float vv[8] = {v0.x, v0.y, v0.z, v0.w, v1.x, v1.y, v1.z, v1.w};
#pragma unroll
            for (int j = 0; j < 8; ++j) {
                float f = RELU_IN ? fmaxf(vv[j], 0.f) : vv[j];
                uint32_t hi = f2tf32(f);
                uint32_t lo = f2tf32(f - __uint_as_float(hi));
                As_hi[(akoff + j) * APAD + arow] = hi;
                As_lo[(akoff + j) * APAD + arow] = lo;
            }
        }
        // ---- stage W, split hi/lo ----
        if (NCOLS == 128) {
            int brow  = tid >> 1;
            int bkoff = (tid & 1) * 8;
            float4 v0 = *reinterpret_cast<const float4*>(W + (size_t)brow * 128 + k0 + bkoff);
            float4 v1 = *reinterpret_cast<const float4*>(W + (size_t)brow * 128 + k0 + bkoff + 4);
            float vv[8] = {v0.x, v0.y, v0.z, v0.w, v1.x, v1.y, v1.z, v1.w};
#pragma unroll
            for (int j = 0; j < 8; ++j) {
                uint32_t hi = f2tf32(vv[j]);
                uint32_t lo = f2tf32(vv[j] - __uint_as_float(hi));
                Bs_hi[(bkoff + j) * BPAD + brow] = hi;
                Bs_lo[(bkoff + j) * BPAD + brow] = lo;
            }
        } else {
            int brow  = tid >> 2;              // 0..63
            int bkoff = (tid & 3) * 4;
            float4 v = *reinterpret_cast<const float4*>(W + (size_t)brow * 128 + k0 + bkoff);
            float vv[4] = {v.x, v.y, v.z, v.w};
#pragma unroll
            for (int j = 0; j < 4; ++j) {
                uint32_t hi = f2tf32(vv[j]);
                uint32_t lo = f2tf32(vv[j] - __uint_as_float(hi));
                Bs_hi[(bkoff + j) * BPAD + brow] = hi;
                Bs_lo[(bkoff + j) * BPAD + brow] = lo;
            }
        }
        __syncthreads();

        // ---- 2 mma k-steps per staged tile ----
#pragma unroll
        for (int ks = 0; ks < 2; ++ks) {
            const int kb = ks * 8;
            uint32_t a_hi[2][4], a_lo[2][4];
#pragma unroll
            for (int mt = 0; mt < 2; ++mt) {
                int mrow = warp_m * 32 + mt * 16 + g;
                a_hi[mt][0] = As_hi[(kb + t) * APAD + mrow];
                a_hi[mt][1] = As_hi[(kb + t) * APAD + mrow + 8];
                a_hi[mt][2] = As_hi[(kb + t + 4) * APAD + mrow];
                a_hi[mt][3] = As_hi[(kb + t + 4) * APAD + mrow + 8];
                a_lo[mt][0] = As_lo[(kb + t) * APAD + mrow];
                a_lo[mt][1] = As_lo[(kb + t) * APAD + mrow + 8];
                a_lo[mt][2] = As_lo[(kb + t + 4) * APAD + mrow];
                a_lo[mt][3] = As_lo[(kb + t + 4) * APAD + mrow + 8];
            }
#pragma unroll
            for (int nt = 0; nt < NT; ++nt) {
                int ncol = warp_n * (NCOLS / 2) + nt * 8 + g;
                uint32_t b_hi0 = Bs_hi[(kb + t) * BPAD + ncol];
                uint32_t b_hi1 = Bs_hi[(kb + t + 4) * BPAD + ncol];
                uint32_t b_lo0 = Bs_lo[(kb + t) * BPAD + ncol];
                uint32_t b_lo1 = Bs_lo[(kb + t + 4) * BPAD + ncol];
#pragma unroll
                for (int mt = 0; mt < 2; ++mt) {
                    mma_tf32(acc[mt][nt], a_hi[mt], b_hi0, b_hi1);
                    mma_tf32(acc[mt][nt], a_hi[mt], b_lo0, b_lo1);
                    mma_tf32(acc[mt][nt], a_lo[mt], b_hi0, b_hi1);
                }
            }
        }
        __syncthreads();
    }

    // ---- store C: frag (row g / g+8, col 2t / 2t+1) ----
#pragma unroll
    for (int mt = 0; mt < 2; ++mt) {
#pragma unroll
        for (int half = 0; half < 2; ++half) {
            int row = blockRow + warp_m * 32 + mt * 16 + half * 8 + g;
            if (row < M) {
#pragma unroll
                for (int nt = 0; nt < NT; ++nt) {
                    int col = warp_n * (NCOLS / 2) + nt * 8 + 2 * t;
                    float2 o = make_float2(acc[mt][nt][half * 2], acc[mt][nt][half * 2 + 1]);
                    *reinterpret_cast<float2*>(C + (size_t)row * NCOLS + col) = o;
                }
            }
        }
    }
}

// ---------------------------------------------------------------------------
// Gather SPMM, 128-wide: one warp per dst node, 4-edge unroll for MLP.
// ---------------------------------------------------------------------------
__global__ __launch_bounds__(256) void gather128_kernel(
    const float* __restrict__ Y, float* __restrict__ S, int n)
{
    int gid  = blockIdx.x * blockDim.x + threadIdx.x;
    int d    = gid >> 5;
    int lane = threadIdx.x & 31;
    if (d >= n) return;
    int beg = g_off[d], end = g_off[d + 1];

    float4 acc = make_float4(0.f, 0.f, 0.f, 0.f);
    int e = beg;
    for (; e + 3 < end; e += 4) {
        int2 p0 = __ldg(&g_edges[e]);
        int2 p1 = __ldg(&g_edges[e + 1]);
        int2 p2 = __ldg(&g_edges[e + 2]);
        int2 p3 = __ldg(&g_edges[e + 3]);
        float4 f0 = *reinterpret_cast<const float4*>(Y + (size_t)p0.x * 128 + lane * 4);
        float4 f1 = *reinterpret_cast<const float4*>(Y + (size_t)p1.x * 128 + lane * 4);
        float4 f2 = *reinterpret_cast<const float4*>(Y + (size_t)p2.x * 128 + lane * 4);
        float4 f3 = *reinterpret_cast<const float4*>(Y + (size_t)p3.x * 128 + lane * 4);
        float v0 = __int_as_float(p0.y), v1 = __int_as_float(p1.y);
        float v2 = __int_as_float(p2.y), v3 = __int_as_float(p3.y);
        acc.x = fmaf(v0, f0.x, acc.x); acc.y = fmaf(v0, f0.y, acc.y);
        acc.z = fmaf(v0, f0.z, acc.z); acc.w = fmaf(v0, f0.w, acc.w);
        acc.x = fmaf(v1, f1.x, acc.x); acc.y = fmaf(v1, f1.y, acc.y);
        acc.z = fmaf(v1, f1.z, acc.z); acc.w = fmaf(v1, f1.w, acc.w);
        acc.x = fmaf(v2, f2.x, acc.x); acc.y = fmaf(v2, f2.y, acc.y);
        acc.z = fmaf(v2, f2.z, acc.z); acc.w = fmaf(v2, f2.w, acc.w);
        acc.x = fmaf(v3, f3.x, acc.x); acc.y = fmaf(v3, f3.y, acc.y);
        acc.z = fmaf(v3, f3.z, acc.z); acc.w = fmaf(v3, f3.w, acc.w);
    }
    for (; e < end; ++e) {
        int2 p = __ldg(&g_edges[e]);
        float v = __int_as_float(p.y);
        float4 f = *reinterpret_cast<const float4*>(Y + (size_t)p.x * 128 + lane * 4);
        acc.x = fmaf(v, f.x, acc.x); acc.y = fmaf(v, f.y, acc.y);
        acc.z = fmaf(v, f.z, acc.z); acc.w = fmaf(v, f.w, acc.w);
    }
    *reinterpret_cast<float4*>(S + (size_t)d * 128 + lane * 4) = acc;
}

// ---------------------------------------------------------------------------
// Gather SPMM, 64-wide, fused with row softmax: warp per node, 2 floats/lane.
// ---------------------------------------------------------------------------
__global__ __launch_bounds__(256) void gather64_softmax_kernel(
    const float* __restrict__ Y, float* __restrict__ out, int n)
{
    int gid  = blockIdx.x * blockDim.x + threadIdx.x;
    int d    = gid >> 5;
    int lane = threadIdx.x & 31;
    if (d >= n) return;
    int beg = g_off[d], end = g_off[d + 1];

    float2 acc = make_float2(0.f, 0.f);
    int e = beg;
    for (; e + 3 < end; e += 4) {
        int2 p0 = __ldg(&g_edges[e]);
        int2 p1 = __ldg(&g_edges[e + 1]);
        int2 p2 = __ldg(&g_edges[e + 2]);
        int2 p3 = __ldg(&g_edges[e + 3]);
        float2 f0 = *reinterpret_cast<const float2*>(Y + (size_t)p0.x * 64 + lane * 2);
        float2 f1 = *reinterpret_cast<const float2*>(Y + (size_t)p1.x * 64 + lane * 2);
        float2 f2 = *reinterpret_cast<const float2*>(Y + (size_t)p2.x * 64 + lane * 2);
        float2 f3 = *reinterpret_cast<const float2*>(Y + (size_t)p3.x * 64 + lane * 2);
        float v0 = __int_as_float(p0.y), v1 = __int_as_float(p1.y);
        float v2 = __int_as_float(p2.y), v3 = __int_as_float(p3.y);
        acc.x = fmaf(v0, f0.x, acc.x); acc.y = fmaf(v0, f0.y, acc.y);
        acc.x = fmaf(v1, f1.x, acc.x); acc.y = fmaf(v1, f1.y, acc.y);
        acc.x = fmaf(v2, f2.x, acc.x); acc.y = fmaf(v2, f2.y, acc.y);
        acc.x = fmaf(v3, f3.x, acc.x); acc.y = fmaf(v3, f3.y, acc.y);
    }
    for (; e < end; ++e) {
        int2 p = __ldg(&g_edges[e]);
        float v = __int_as_float(p.y);
        float2 f = *reinterpret_cast<const float2*>(Y + (size_t)p.x * 64 + lane * 2);
        acc.x = fmaf(v, f.x, acc.x); acc.y = fmaf(v, f.y, acc.y);
    }

    // warp softmax over the 64-value row (2 per lane)
    float m = fmaxf(acc.x, acc.y);
#pragma unroll
    for (int o = 16; o; o >>= 1) m = fmaxf(m, __shfl_xor_sync(0xffffffffu, m, o));
    float e0 = __expf(acc.x - m);
    float e1 = __expf(acc.y - m);
    float ssum = e0 + e1;
#pragma unroll
    for (int o = 16; o; o >>= 1) ssum += __shfl_xor_sync(0xffffffffu, ssum, o);
    float inv = 1.f / ssum;
    *reinterpret_cast<float2*>(out + (size_t)d * 64 + lane * 2) =
        make_float2(e0 * inv, e1 * inv);
}

// ---------------------------------------------------------------------------
// Launch. Inputs: x, vals, W1, W2, src, dst. Output fp32 [N, 64].
// ---------------------------------------------------------------------------
extern "C" void kernel_launch(void* const* d_in, const int* in_sizes, int n_in,
                              void* d_out, int out_size)
{
    const float* x    = (const float*)d_in[0];
    const float* vals = (const float*)d_in[1];
    const float* W1   = (const float*)d_in[2];
    const float* W2   = (const float*)d_in[3];
    const int*   src  = (const int*)d_in[4];
    const int*   dst  = (const int*)d_in[5];
    float*       out  = (float*)d_out;

    const int M = in_sizes[0] / NF;   // 50000
    const int E = in_sizes[1];        // 800000

    float *y1, *s1, *y2;
    int* degp;
    cudaGetSymbolAddress((void**)&y1, g_y1);
    cudaGetSymbolAddress((void**)&s1, g_s1);
    cudaGetSymbolAddress((void**)&y2, g_y2);
    cudaGetSymbolAddress((void**)&degp, g_deg);

    // --- CSR build (by dst) ---
    cudaMemsetAsync(degp, 0, M * sizeof(int));
    hist_kernel<<<(E + 255) / 256, 256>>>(dst, E);
    int nb = (M + SCAN_B - 1) / SCAN_B;                 // 98
    scan1_kernel<<<nb, SCAN_B>>>(M);
    scan2_kernel<<<1, SCAN_B>>>(nb);
    scan3_kernel<<<(M + 255) / 256, 256>>>(M, E);
    permute_kernel<<<(E + 255) / 256, 256>>>(src, dst, vals, E);

    // --- pipeline ---
    int gemmBlocks = (M + 127) / 128;
    gemm_tc_kernel<128, false><<<gemmBlocks, 256>>>(x, W1, y1, M);          // y1 = x @ W1^T
    gather128_kernel<<<(M * 32 + 255) / 256, 256>>>(y1, s1, M);             // s1 = A @ y1
    gemm_tc_kernel<64, true><<<gemmBlocks, 256>>>(s1, W2, y2, M);           // y2 = relu(s1) @ W2^T
    gather64_softmax_kernel<<<(M * 32 + 255) / 256, 256>>>(y2, out, M);     // out = softmax(A @ y2)
}